// round 6
// baseline (speedup 1.0000x reference)
#include <cuda_runtime.h>
#include <math.h>

// Scratch (device globals; no allocation allowed)
__device__ float g_PEX[32 * 256];        // pos_enc(j) @ W1[0:64]
__device__ float g_PEY[32 * 256];        // pos_enc(r) @ W1[64:128] + b1
__device__ float g_PEB[32 * 256];        // pos_enc(c) @ Wb1[32:96] + bb1
__device__ float g_S  [64];              // row sums of x
__device__ float g_u  [64 * 256];        // u[b,h] = sum_i x[b,i]*h[b,i,h]
__device__ float g_out[64 * 1024];       // einsum output (pre-bias)

__device__ __forceinline__ float tanh_fast(float v) {
    float y;
    asm("tanh.approx.f32 %0, %1;" : "=f"(y) : "f"(v));
    return y;
}

// ---------------------------------------------------------------------------
// K1: positional-encoding projections + row sums. 96 blocks.
// blocks [0,32): PEX/PEY/PEB for position p=blk
// blocks [32,96): S[b]
// ---------------------------------------------------------------------------
__global__ void k1_setup(const float* __restrict__ x,
                         const float* __restrict__ W1,
                         const float* __restrict__ b1,
                         const float* __restrict__ Wb1,
                         const float* __restrict__ bb1) {
    int blk = blockIdx.x;
    int t = threadIdx.x;

    if (blk < 32) {
        __shared__ float pe[64];
        if (t < 64) {
            int k = t >> 1;
            double invf = exp(-(double)(2 * k) / 64.0 * log(10000.0));
            float ang = (float)((double)blk * invf);
            pe[t] = (t & 1) ? cosf(ang) : sinf(ang);
        }
        __syncthreads();
        float ax = 0.f, ay = 0.f, ab = 0.f;
#pragma unroll
        for (int d = 0; d < 64; d++) {
            float p = pe[d];
            ax = fmaf(p, W1[d * 256 + t], ax);
            ay = fmaf(p, W1[(64 + d) * 256 + t], ay);
            ab = fmaf(p, Wb1[(32 + d) * 256 + t], ab);
        }
        g_PEX[blk * 256 + t] = ax;
        g_PEY[blk * 256 + t] = ay + b1[t];
        g_PEB[blk * 256 + t] = ab + bb1[t];
    } else {
        int b = blk - 32;
        __shared__ float red[256];
        float s = 0.f;
        for (int i = t; i < 1024; i += 256) s += x[b * 1024 + i];
        red[t] = s;
        __syncthreads();
        for (int off = 128; off > 0; off >>= 1) {
            if (t < off) red[t] += red[t + off];
            __syncthreads();
        }
        if (t == 0) g_S[b] = red[0];
    }
}

// ---------------------------------------------------------------------------
// K2: u[b,h] = sum_{r,j} x[b, r*32+j] * tanh(A[j,h] + PEY[r,h])
// with A[j,h] = PEX[j,h] + sum_c x[b, j*32+c] * W1[128+c, h] computed
// cooperatively in smem (W1 slice loaded once per block).
// grid 512 blocks: (b, h-chunk of 32). 256 threads.
// ---------------------------------------------------------------------------
__global__ void k2_u(const float* __restrict__ x,
                     const float* __restrict__ W1) {
    int b = blockIdx.x >> 3;
    int hc = blockIdx.x & 7;
    int t = threadIdx.x;
    int hl = t & 31;
    int rg = t >> 5;
    int h = hc * 32 + hl;

    __shared__ float xs[1024];
    __shared__ float W1s[32][33];
    __shared__ float As[32][33];

    for (int i = t; i < 1024; i += 256) xs[i] = x[b * 1024 + i];
    for (int i = t; i < 1024; i += 256) {
        int c = i >> 5, cl = i & 31;
        W1s[c][cl] = W1[(128 + c) * 256 + hc * 32 + cl];
    }
    __syncthreads();

    // A[j][hl] for j = rg*4 .. rg*4+3
#pragma unroll
    for (int q = 0; q < 4; q++) {
        int j = rg * 4 + q;
        float a = g_PEX[j * 256 + h];
        const float* xj = &xs[j * 32];
#pragma unroll
        for (int c = 0; c < 32; c++)
            a = fmaf(xj[c], W1s[c][hl], a);
        As[j][hl] = a;
    }
    __syncthreads();

    float A[32];
#pragma unroll
    for (int j = 0; j < 32; j++) A[j] = As[j][hl];

    float acc = 0.f;
#pragma unroll
    for (int rr = 0; rr < 4; rr++) {
        int r = rg * 4 + rr;
        float C = g_PEY[r * 256 + h];
        const float* xr = &xs[r * 32];
#pragma unroll
        for (int j = 0; j < 32; j++)
            acc = fmaf(xr[j], tanh_fast(A[j] + C), acc);
    }

    __shared__ float red[8][33];
    red[rg][hl] = acc;
    __syncthreads();
    if (t < 32) {
        float s = 0.f;
#pragma unroll
        for (int p = 0; p < 8; p++) s += red[p][t];
        g_u[b * 256 + hc * 32 + t] = s;
    }
}

// ---------------------------------------------------------------------------
// K3: out[b,o] = u[b,:] @ W2[:,o] + S[b]*b2[o]
// grid 128 blocks: (b-group of 8) x (o-chunk of 64). 256 threads.
// ---------------------------------------------------------------------------
__global__ void k3_out(const float* __restrict__ W2,
                       const float* __restrict__ b2) {
    int bg = blockIdx.x >> 4;
    int oc = blockIdx.x & 15;
    int t = threadIdx.x;
    int ol = t & 63;
    int hg = t >> 6;
    int o = oc * 64 + ol;

    __shared__ float us[256][8];
    __shared__ float Ss[8];
    for (int i = t; i < 256 * 8; i += 256) {
        int h = i >> 3, bb = i & 7;
        us[h][bb] = g_u[(bg * 8 + bb) * 256 + h];
    }
    if (t < 8) Ss[t] = g_S[bg * 8 + t];
    __syncthreads();

    float acc[8] = {0.f, 0.f, 0.f, 0.f, 0.f, 0.f, 0.f, 0.f};
#pragma unroll 8
    for (int hh = 0; hh < 64; hh++) {
        int h = hg * 64 + hh;
        float w = W2[h * 1024 + o];
#pragma unroll
        for (int bb = 0; bb < 8; bb++)
            acc[bb] = fmaf(us[h][bb], w, acc[bb]);
    }

    __shared__ float red[4][8][64];
#pragma unroll
    for (int bb = 0; bb < 8; bb++) red[hg][bb][ol] = acc[bb];
    __syncthreads();

#pragma unroll
    for (int pass = 0; pass < 2; pass++) {
        int bb = hg + pass * 4;
        float s = red[0][bb][ol] + red[1][bb][ol] + red[2][bb][ol] + red[3][bb][ol];
        s = fmaf(Ss[bb], b2[o], s);
        g_out[(bg * 8 + bb) * 1024 + o] = s;
    }
}

// ---------------------------------------------------------------------------
// K4: bias hypernetwork + final add, register-resident weights.
// Block = 8 rows of (b, c0..c0+7); 256 blocks x 512 threads.
// Threads split in two halves; half hf handles rows hf*4..hf*4+3.
// Layer1: thread col tt holds Wb1[:,tt] in 32 regs (L1-dedup across halves).
// Layer2: thread (hg,m) holds Wb2[hg*32..+32, m] in 32 regs.
// ---------------------------------------------------------------------------
__global__ void __launch_bounds__(512) k4_bias(
        const float* __restrict__ Wb1,
        const float* __restrict__ Wb2,
        const float* __restrict__ bb2,
        float* __restrict__ y) {
    int blk = blockIdx.x;           // 0..255
    int b = blk >> 2;               // 0..63
    int c0 = (blk & 3) * 8;         // chunk base
    int t = threadIdx.x;            // 0..511
    int tt = t & 255;               // column within hidden dim
    int hf = t >> 8;                // half: row group

    __shared__ float os[8][32];     // out chunk values for 8 rows
    __shared__ float H[8][256];     // tanh hidden
    __shared__ float red[8][8][32]; // [hg][r][m]

    // load os: first 256 threads -> (r = tt>>5, k = tt&31)
    if (t < 256)
        os[tt >> 5][tt & 31] = g_out[b * 1024 + (c0 + (tt >> 5)) * 32 + (tt & 31)];

    // Wb1 column tt (coalesced; halves duplicate -> L1 hit)
    float w1[32];
#pragma unroll
    for (int k = 0; k < 32; k++) w1[k] = Wb1[k * 256 + tt];

    // Wb2 slice
    int hg = tt >> 5, m = tt & 31;
    float w2[32];
#pragma unroll
    for (int hh = 0; hh < 32; hh++) w2[hh] = Wb2[(hg * 32 + hh) * 32 + m];

    __syncthreads();

    // Layer 1: rows hf*4 .. hf*4+3
#pragma unroll
    for (int rr = 0; rr < 4; rr++) {
        int r = hf * 4 + rr;
        float a = g_PEB[(c0 + r) * 256 + tt];
        const float4* o4 = (const float4*)os[r];
#pragma unroll
        for (int q = 0; q < 8; q++) {
            float4 o = o4[q];
            a = fmaf(o.x, w1[4 * q + 0], a);
            a = fmaf(o.y, w1[4 * q + 1], a);
            a = fmaf(o.z, w1[4 * q + 2], a);
            a = fmaf(o.w, w1[4 * q + 3], a);
        }
        H[r][tt] = tanh_fast(a);
    }
    __syncthreads();

    // Layer 2 partials: rows hf*4 .. hf*4+3
#pragma unroll
    for (int rr = 0; rr < 4; rr++) {
        int r = hf * 4 + rr;
        float s = 0.f;
        const float4* h4 = (const float4*)&H[r][hg * 32];
#pragma unroll
        for (int q = 0; q < 8; q++) {
            float4 hv = h4[q];
            s = fmaf(hv.x, w2[4 * q + 0], s);
            s = fmaf(hv.y, w2[4 * q + 1], s);
            s = fmaf(hv.z, w2[4 * q + 2], s);
            s = fmaf(hv.w, w2[4 * q + 3], s);
        }
        red[hg][r][m] = s;
    }
    __syncthreads();

    // Final: first 256 threads -> (r = tt>>5, m = tt&31)
    if (t < 256) {
        int r = tt >> 5, mm = tt & 31;
        float bias = bb2[mm];
#pragma unroll
        for (int p = 0; p < 8; p++) bias += red[p][r][mm];
        y[b * 1024 + (c0 + r) * 32 + mm] = os[r][mm] + bias;
    }
}

extern "C" void kernel_launch(void* const* d_in, const int* in_sizes, int n_in,
                              void* d_out, int out_size) {
    const float* x   = (const float*)d_in[0];
    // d_in[1] = output_size (int) — fixed at 1024 by the problem shapes
    const float* W1  = (const float*)d_in[2];
    const float* b1  = (const float*)d_in[3];
    const float* W2  = (const float*)d_in[4];
    const float* b2  = (const float*)d_in[5];
    const float* Wb1 = (const float*)d_in[6];
    const float* bb1 = (const float*)d_in[7];
    const float* Wb2 = (const float*)d_in[8];
    const float* bb2 = (const float*)d_in[9];
    float* y = (float*)d_out;

    k1_setup<<<96, 256>>>(x, W1, b1, Wb1, bb1);
    k2_u<<<512, 256>>>(x, W1);
    k3_out<<<128, 256>>>(W2, b2);
    k4_bias<<<256, 512>>>(Wb1, Wb2, bb2, y);
}